// round 13
// baseline (speedup 1.0000x reference)
#include <cuda_runtime.h>
#include <math.h>

#define Hh 64
#define Ff 10
#define Tt 60
#define Dd 6
#define Bb 2048

typedef unsigned long long ull;

// f32 recurrent weights as natural (gate0,gate1) f32x2 pairs per gate-role g:
//   g=0: (G0,G1) = (U_i,U_ste);  g=1: (U_c,U_o)
// g_Uf2[g][j*32+lane] = { (G0,G1)@h=lane , (G0,G1)@h=lane+32 }
__device__ __align__(16) ulonglong2 g_Uf2[2][Hh * 32];

__global__ void prep_kernel(const float* __restrict__ Ui, const float* __restrict__ Us,
                            const float* __restrict__ Uc, const float* __restrict__ Uo) {
    int idx = blockIdx.x * blockDim.x + threadIdx.x;   // [0, 2*64*32)
    if (idx < 2 * Hh * 32) {
        int g = idx >> 11, r = idx & 2047;
        int j = r >> 5, lane = r & 31;
        const float* G0 = g ? Uc : Ui;
        const float* G1 = g ? Uo : Us;
        float2 lo = make_float2(G0[j * Hh + lane],      G1[j * Hh + lane]);
        float2 hi = make_float2(G0[j * Hh + lane + 32], G1[j * Hh + lane + 32]);
        ulonglong2 v;
        v.x = *reinterpret_cast<ull*>(&lo);
        v.y = *reinterpret_cast<ull*>(&hi);
        g_Uf2[g][r] = v;
    }
}

__device__ __forceinline__ float hsig(float v) {
    return __saturatef(fmaf(v, 0.16666667f, 0.5f));
}
__device__ __forceinline__ ull pack2(float lo, float hi) {
    ull r; asm("mov.b64 %0, {%1, %2};" : "=l"(r) : "f"(lo), "f"(hi)); return r;
}
__device__ __forceinline__ ull fma2(ull a, ull b, ull c) {
    ull d; asm("fma.rn.f32x2 %0, %1, %2, %3;" : "=l"(d) : "l"(a), "l"(b), "l"(c)); return d;
}
__device__ __forceinline__ ull mul2(ull a, ull b) {
    ull d; asm("mul.rn.f32x2 %0, %1, %2;" : "=l"(d) : "l"(a), "l"(b)); return d;
}
__device__ __forceinline__ ull add2(ull a, ull b) {
    ull d; asm("add.rn.f32x2 %0, %1, %2;" : "=l"(d) : "l"(a), "l"(b)); return d;
}
__device__ __forceinline__ float2 unpack2(ull v) {
    float lo, hi; asm("mov.b64 {%0, %1}, %2;" : "=f"(lo), "=f"(hi) : "l"(v));
    return make_float2(lo, hi);
}
// tanh(x) = 1 - 2/(exp(2x)+1): MUFU.EX2 + MUFU.RCP, abs err ~1e-6
__device__ __forceinline__ float ftanh(float x) {
    float e = __expf(2.0f * x);
    float r;
    asm("rcp.approx.f32 %0, %1;" : "=f"(r) : "f"(e + 1.0f));
    return fmaf(-2.0f, r, 1.0f);
}

// One j step: f32 (g0,g1) U pairs x dup-h pairs, 4 batches, 2 hslots.
#define JSTEP(UPTR, HPTR, UFPTR, JJ)                                          \
    do {                                                                      \
        ulonglong2 u  = (UPTR)[(JJ) * 32];             /* LDS.128 */          \
        ulonglong2 hA = *(const ulonglong2*)&(HPTR)[(JJ) * 4];                \
        ulonglong2 hB = *(const ulonglong2*)&(HPTR)[(JJ) * 4 + 2];            \
        acc[0][0] = fma2(hA.x, u.x, acc[0][0]);                               \
        acc[1][0] = fma2(hA.x, u.y, acc[1][0]);                               \
        acc[0][1] = fma2(hA.y, u.x, acc[0][1]);                               \
        acc[1][1] = fma2(hA.y, u.y, acc[1][1]);                               \
        acc[0][2] = fma2(hB.x, u.x, acc[0][2]);                               \
        acc[1][2] = fma2(hB.x, u.y, acc[1][2]);                               \
        acc[0][3] = fma2(hB.y, u.x, acc[0][3]);                               \
        acc[1][3] = fma2(hB.y, u.y, acc[1][3]);                               \
        if (duty) {                                                           \
            ull hown = w ? (fb ? hB.y : hB.x) : (fb ? hA.y : hA.x);           \
            af = fmaf(unpack2(hown).x, (UFPTR)[(JJ)], af);                    \
        }                                                                     \
    } while (0)

// Block = 128 threads = TWO independent gate-split pairs (pair = tid>>6),
// each pair handling 4 batches exactly like R12, sharing one 64KB f32 U
// staging in dynamic shared. Pairs sync on their own named barrier and walk
// j starting at opposite halves to decorrelate LDS bursts.
__global__ __launch_bounds__(128) void sfm_kernel(
    const float* __restrict__ x,
    const float* __restrict__ W_i,   const float* __restrict__ b_i,
    const float* __restrict__ W_ste, const float* __restrict__ b_ste,
    const float* __restrict__ W_fre, const float* __restrict__ U_fre, const float* __restrict__ b_fre,
    const float* __restrict__ W_c,   const float* __restrict__ b_c,
    const float* __restrict__ W_o,   const float* __restrict__ b_o,
    const float* __restrict__ U_a,   const float* __restrict__ b_a,
    const float* __restrict__ W_p,   const float* __restrict__ b_p,
    float* __restrict__ out)
{
    extern __shared__ __align__(16) char dynraw[];
    ulonglong2* dynU = reinterpret_cast<ulonglong2*>(dynraw);   // [g][j][lane], 64 KB

    __shared__ __align__(16) float4 sh_x4[2][Tt][Dd];   // per pair: (b0..b3)
    __shared__ __align__(16) ull    sh_hd[2][Hh][4];    // per pair: dup (h,h) [col][b]
    __shared__ __align__(16) ull    sh_ex[2][2][32][4]; // [pair][writer w][lane][hs*2+bl]
    __shared__ float                sh_UfT[Ff * 65];    // [f][j], padded rows
    __shared__ ull                  sh_mpk[Tt];         // packed nibble idx m(t,f)
    __shared__ __align__(16) ulonglong2 sh_tbld[16];    // {(cos,cos),(sin,sin)} dup pairs

    const int tid  = threadIdx.x;
    const int lane = tid & 31;
    const int w2   = tid >> 5;            // warp 0..3
    const int p    = w2 >> 1;             // pair 0/1
    const int w    = w2 & 1;              // gate role: 0=(i,ste), 1=(c,o)
    const int bbase = blockIdx.x * 8;     // 8 batches per block (4 per pair)

    // ---- one-time staging (all 128 threads) ----
    {   // U: 4096 uint4 = 64 KB
        const uint4* gsrc = reinterpret_cast<const uint4*>(&g_Uf2[0][0]);
        uint4* sdst = reinterpret_cast<uint4*>(dynraw);
        for (int i = tid; i < 4096; i += 128) sdst[i] = gsrc[i];
    }
    const float* xg = x + (size_t)bbase * (Tt * Dd);
    for (int i = tid; i < 2 * Tt * Dd; i += 128) {
        int pp = i / (Tt * Dd), r = i % (Tt * Dd);
        sh_x4[pp][r / Dd][r % Dd] =
            make_float4(xg[(4 * pp + 0) * Tt * Dd + r], xg[(4 * pp + 1) * Tt * Dd + r],
                        xg[(4 * pp + 2) * Tt * Dd + r], xg[(4 * pp + 3) * Tt * Dd + r]);
    }
    for (int i = tid; i < Ff * Hh; i += 128) {
        int f = i >> 6, j = i & 63;
        sh_UfT[f * 65 + j] = U_fre[j * Ff + f];
    }
    for (int i = tid; i < Tt; i += 128) {
        ull v = 0;
#pragma unroll
        for (int f = 1; f < Ff; f++)
            v |= (ull)(((i + 1) * f) % Ff) << (4 * f);
        sh_mpk[i] = v;
    }
    if (tid < Ff) {
        float s, c;
        sincosf((float)tid * 0.62831853071795864769f, &s, &c);   // 2*pi/10
        sh_tbld[tid] = make_ulonglong2(pack2(c, c), pack2(s, s));
    }
    if (tid < Hh) {
#pragma unroll
        for (int b = 0; b < 4; b++) { sh_hd[0][tid][b] = 0ull; sh_hd[1][tid][b] = 0ull; }
    }

    // ---- per-lane constants ----
    const int h0 = lane, h1 = lane + 32;
    const float* Wg0 = w ? W_c : W_i;
    const float* Wg1 = w ? W_o : W_ste;
    const float* bg0 = w ? b_c : b_i;
    const float* bg1 = w ? b_o : b_ste;
    ull Wp_[2][Dd];   // W as natural (g0,g1) pairs: [hslot][d]
#pragma unroll
    for (int d = 0; d < Dd; d++) {
        Wp_[0][d] = pack2(Wg0[d * Hh + h0], Wg1[d * Hh + h0]);
        Wp_[1][d] = pack2(Wg0[d * Hh + h1], Wg1[d * Hh + h1]);
    }
    const ull bp_[2] = { pack2(bg0[h0], bg1[h0]), pack2(bg0[h1], bg1[h1]) };
    const ull ba_p = pack2(b_a[h0], b_a[h1]);
    ull ua_d[Ff];
#pragma unroll
    for (int f = 0; f < Ff; f++) { float u = U_a[f]; ua_d[f] = pack2(u, u); }

    // fre duty: lanes 0..19 -> local batch fb = lane/10, freq ff = lane%10.
    const bool duty = (lane < 2 * Ff);
    const int  fb = lane / Ff, ff = lane % Ff;
    float wfre[Dd];
#pragma unroll
    for (int d = 0; d < Dd; d++) wfre[d] = W_fre[d * Ff + ff];
    const float bfre = b_fre[ff];

    // Oscillator state, hslot-packed: sre_p[bl][f] = (sre@h0, sre@h1)
    ull sre_p[2][Ff], sim_p[2][Ff];
#pragma unroll
    for (int bl = 0; bl < 2; bl++)
#pragma unroll
        for (int f = 0; f < Ff; f++) { sre_p[bl][f] = 0ull; sim_p[bl][f] = 0ull; }

    float hlast[2][2];   // [bl][hslot]

    __syncthreads();   // staging visible to both pairs

    // Per-pair loop pointers; pair 1 walks j halves in swapped order.
    const int js = p << 5;
    const ulonglong2* UpA = dynU + (w * Hh + js) * 32 + lane;
    const ulonglong2* UpB = dynU + (w * Hh + (js ^ 32)) * 32 + lane;
    const ull* hbA = &sh_hd[p][js][0];
    const ull* hbB = &sh_hd[p][js ^ 32][0];
    const float* ufA = &sh_UfT[ff * 65 + js];
    const float* ufB = &sh_UfT[ff * 65 + (js ^ 32)];
    const int barid = p + 1;

    for (int t = 0; t < Tt; t++) {
        // ---- seeds: acc[hs][b] = (g0,g1) bias + x_t @ (Wg0,Wg1) ----
        ull acc[2][4];
#pragma unroll
        for (int b = 0; b < 4; b++) { acc[0][b] = bp_[0]; acc[1][b] = bp_[1]; }
        float af = bfre;
#pragma unroll
        for (int d = 0; d < Dd; d++) {
            float4 xv = sh_x4[p][t][d];          // LDS.128 broadcast
            ull x0 = pack2(xv.x, xv.x);
            ull x1 = pack2(xv.y, xv.y);
            ull x2 = pack2(xv.z, xv.z);
            ull x3 = pack2(xv.w, xv.w);
            acc[0][0] = fma2(x0, Wp_[0][d], acc[0][0]);
            acc[1][0] = fma2(x0, Wp_[1][d], acc[1][0]);
            acc[0][1] = fma2(x1, Wp_[0][d], acc[0][1]);
            acc[1][1] = fma2(x1, Wp_[1][d], acc[1][1]);
            acc[0][2] = fma2(x2, Wp_[0][d], acc[0][2]);
            acc[1][2] = fma2(x2, Wp_[1][d], acc[1][2]);
            acc[0][3] = fma2(x3, Wp_[0][d], acc[0][3]);
            acc[1][3] = fma2(x3, Wp_[1][d], acc[1][3]);
            float xd = fb ? (w ? xv.w : xv.y) : (w ? xv.z : xv.x);
            af = fmaf(xd, wfre[d], af);
        }

        // ---- recurrent matmul: f32 U pairs, no conversions, wrapped j halves ----
#pragma unroll 8
        for (int jj = 0; jj < 32; jj++) JSTEP(UpA, hbA, ufA, jj);
#pragma unroll 8
        for (int jj = 0; jj < 32; jj++) JSTEP(UpB, hbB, ufB, jj);
        const float frev = hsig(af);   // valid on duty lanes

        // ---- exchange: send my gate pairs for the PEER's 2 batches ----
        {
            int pb = 2 * (1 - w);
            ulonglong2* dst = reinterpret_cast<ulonglong2*>(&sh_ex[p][w][lane][0]);
            dst[0] = make_ulonglong2(acc[0][pb],     acc[1][pb]);
            dst[1] = make_ulonglong2(acc[0][pb + 1], acc[1][pb + 1]);
        }
        asm volatile("bar.sync %0, 64;" :: "r"(barid) : "memory");
        ull peer[2][2];    // [bl][hs]
        {
            const ulonglong2* src = reinterpret_cast<const ulonglong2*>(&sh_ex[p][1 - w][lane][0]);
            ulonglong2 s0 = src[0], s1 = src[1];
            peer[0][0] = s0.x; peer[0][1] = s0.y;
            peer[1][0] = s1.x; peer[1][1] = s1.y;
        }

        // ---- elementwise tail, hslot-packed f32x2 ----
        const ull mp = sh_mpk[t];
#pragma unroll
        for (int bl = 0; bl < 2; bl++) {
            int b = 2 * w + bl;
            float iv0, sv0, ov0, cv0, iv1, sv1, ov1, cv1;
            {
                float2 mine0 = unpack2(acc[0][b]);
                float2 thrs0 = unpack2(peer[bl][0]);
                float pi0   = w ? thrs0.x : mine0.x;
                float pste0 = w ? thrs0.y : mine0.y;
                float pc0   = w ? mine0.x : thrs0.x;
                float po0   = w ? mine0.y : thrs0.y;
                iv0 = hsig(pi0); sv0 = hsig(pste0); ov0 = hsig(po0);
                cv0 = iv0 * ftanh(pc0);
                float2 mine1 = unpack2(acc[1][b]);
                float2 thrs1 = unpack2(peer[bl][1]);
                float pi1   = w ? thrs1.x : mine1.x;
                float pste1 = w ? thrs1.y : mine1.y;
                float pc1   = w ? mine1.x : thrs1.x;
                float po1   = w ? mine1.y : thrs1.y;
                iv1 = hsig(pi1); sv1 = hsig(pste1); ov1 = hsig(po1);
                cv1 = iv1 * ftanh(pc1);
            }
            ull sv_p = pack2(sv0, sv1);
            ull cv_p = pack2(cv0, cv1);
            ull acca_p = ba_p;
#pragma unroll
            for (int f = 0; f < Ff; f++) {
                float frf = __shfl_sync(0xffffffffu, frev, bl * Ff + f);
                ull fr_p = pack2(frf, frf);
                ulonglong2 tb = sh_tbld[(int)((mp >> (4 * f)) & 15)];
                ull fv = mul2(sv_p, fr_p);
                ull r = fma2(fv, sre_p[bl][f], mul2(cv_p, tb.x));
                ull m = fma2(fv, sim_p[bl][f], mul2(cv_p, tb.y));
                sre_p[bl][f] = r;
                sim_p[bl][f] = m;
                ull A = fma2(m, m, mul2(r, r));
                acca_p = fma2(A, ua_d[f], acca_p);
            }
            float2 acca = unpack2(acca_p);
            hlast[bl][0] = ov0 * ftanh(acca.x);
            hlast[bl][1] = ov1 * ftanh(acca.y);
        }
        // Publish my 2 batches' h as dup pairs at both columns.
        {
            ulonglong2* r0 = reinterpret_cast<ulonglong2*>(&sh_hd[p][h0][2 * w]);
            ulonglong2* r1 = reinterpret_cast<ulonglong2*>(&sh_hd[p][h1][2 * w]);
            *r0 = make_ulonglong2(pack2(hlast[0][0], hlast[0][0]),
                                  pack2(hlast[1][0], hlast[1][0]));
            *r1 = make_ulonglong2(pack2(hlast[0][1], hlast[0][1]),
                                  pack2(hlast[1][1], hlast[1][1]));
        }
        asm volatile("bar.sync %0, 64;" :: "r"(barid) : "memory");
    }

    // ---- projection: out[b] = h @ W_p + b_p (warp butterfly over my 2 batches) ----
    {
        float wp0 = W_p[h0], wp1 = W_p[h1];
        float p0 = fmaf(hlast[0][0], wp0, hlast[0][1] * wp1);
        float p1 = fmaf(hlast[1][0], wp0, hlast[1][1] * wp1);
        ull pp = pack2(p0, p1);
#pragma unroll
        for (int off = 16; off >= 1; off >>= 1)
            pp = add2(pp, __shfl_xor_sync(0xffffffffu, pp, off));
        if (lane == 0) {
            float2 r = unpack2(pp);
            float bpv = b_p[0];
            out[bbase + 4 * p + 2 * w]     = r.x + bpv;
            out[bbase + 4 * p + 2 * w + 1] = r.y + bpv;
        }
    }
}

extern "C" void kernel_launch(void* const* d_in, const int* in_sizes, int n_in,
                              void* d_out, int out_size) {
    const float* x     = (const float*)d_in[0];
    const float* W_i   = (const float*)d_in[1];
    const float* U_i   = (const float*)d_in[2];
    const float* b_i   = (const float*)d_in[3];
    const float* W_ste = (const float*)d_in[4];
    const float* U_ste = (const float*)d_in[5];
    const float* b_ste = (const float*)d_in[6];
    const float* W_fre = (const float*)d_in[7];
    const float* U_fre = (const float*)d_in[8];
    const float* b_fre = (const float*)d_in[9];
    const float* W_c   = (const float*)d_in[10];
    const float* U_c   = (const float*)d_in[11];
    const float* b_c   = (const float*)d_in[12];
    const float* W_o   = (const float*)d_in[13];
    const float* U_o   = (const float*)d_in[14];
    const float* b_o   = (const float*)d_in[15];
    const float* U_a   = (const float*)d_in[16];
    const float* b_a   = (const float*)d_in[17];
    const float* W_p   = (const float*)d_in[18];
    const float* b_p   = (const float*)d_in[19];

    (void)in_sizes; (void)n_in; (void)out_size;

    static int smem_set = 0;
    if (!smem_set) {
        cudaFuncSetAttribute(sfm_kernel, cudaFuncAttributeMaxDynamicSharedMemorySize, 65536);
        smem_set = 1;
    }

    prep_kernel<<<(2 * Hh * 32 + 255) / 256, 256>>>(U_i, U_ste, U_c, U_o);
    sfm_kernel<<<Bb / 8, 128, 65536>>>(x, W_i, b_i, W_ste, b_ste, W_fre, U_fre, b_fre,
                                       W_c, b_c, W_o, b_o, U_a, b_a, W_p, b_p,
                                       (float*)d_out);
}

// round 16
// speedup vs baseline: 1.5026x; 1.5026x over previous
#include <cuda_runtime.h>
#include <cuda_bf16.h>
#include <cstdint>
#include <math.h>

#define Hh 64
#define Ff 10
#define Tt 60
#define Dd 6
#define Bb 2048
#define NBB 8           // batches per block
#define NT 192          // 2 GEMM warps + 4 tail warps

typedef unsigned long long ull;
typedef unsigned int u32;

// bf16 recurrent weights, 2 j's per uint4, per gate-role g (R12-proven layout):
//   g=0: (G0,G1) = (U_i,U_ste);  g=1: (U_c,U_o)
// g_Ub4[g][jp*32+lane] = { bf16x2(G0,G1)@j0,h0 ; @j0,h1 ; @j1,h0 ; @j1,h1 }
__device__ uint4 g_Ub4[2][32 * 32];

__device__ __forceinline__ u32 bpack(float a, float b) {
    __nv_bfloat162 p = __floats2bfloat162_rn(a, b);
    return *reinterpret_cast<u32*>(&p);
}

__global__ void prep_kernel(const float* __restrict__ Ui, const float* __restrict__ Us,
                            const float* __restrict__ Uc, const float* __restrict__ Uo) {
    int idx = blockIdx.x * blockDim.x + threadIdx.x;   // [0, 2*32*32)
    if (idx < 2 * 32 * 32) {
        int g = idx >> 10, r = idx & 1023;
        int jp = r >> 5, lane = r & 31;
        int j0 = 2 * jp, j1 = 2 * jp + 1;
        const float* G0 = g ? Uc : Ui;
        const float* G1 = g ? Uo : Us;
        uint4 v;
        v.x = bpack(G0[j0 * Hh + lane],      G1[j0 * Hh + lane]);
        v.y = bpack(G0[j0 * Hh + lane + 32], G1[j0 * Hh + lane + 32]);
        v.z = bpack(G0[j1 * Hh + lane],      G1[j1 * Hh + lane]);
        v.w = bpack(G0[j1 * Hh + lane + 32], G1[j1 * Hh + lane + 32]);
        g_Ub4[g][r] = v;
    }
}

__device__ __forceinline__ float hsig(float v) {
    return __saturatef(fmaf(v, 0.16666667f, 0.5f));
}
__device__ __forceinline__ ull pack2(float lo, float hi) {
    ull r; asm("mov.b64 %0, {%1, %2};" : "=l"(r) : "f"(lo), "f"(hi)); return r;
}
__device__ __forceinline__ ull fma2(ull a, ull b, ull c) {
    ull d; asm("fma.rn.f32x2 %0, %1, %2, %3;" : "=l"(d) : "l"(a), "l"(b), "l"(c)); return d;
}
__device__ __forceinline__ ull mul2(ull a, ull b) {
    ull d; asm("mul.rn.f32x2 %0, %1, %2;" : "=l"(d) : "l"(a), "l"(b)); return d;
}
__device__ __forceinline__ ull add2(ull a, ull b) {
    ull d; asm("add.rn.f32x2 %0, %1, %2;" : "=l"(d) : "l"(a), "l"(b)); return d;
}
__device__ __forceinline__ float2 unpack2(ull v) {
    float lo, hi; asm("mov.b64 {%0, %1}, %2;" : "=f"(lo), "=f"(hi) : "l"(v));
    return make_float2(lo, hi);
}
// bf16x2(G0,G1) -> f32x2 (G0,G1): ALU filler between LDS and FFMA2.
__device__ __forceinline__ ull bf2f2(u32 u) {
    float lo = __uint_as_float(u << 16);
    float hi = __uint_as_float(u & 0xFFFF0000u);
    return pack2(lo, hi);
}
// tanh(x) = 1 - 2/(exp(2x)+1): MUFU.EX2 + MUFU.RCP, abs err ~1e-6
__device__ __forceinline__ float ftanh(float x) {
    float e = __expf(2.0f * x);
    float r;
    asm("rcp.approx.f32 %0, %1;" : "=f"(r) : "f"(e + 1.0f));
    return fmaf(-2.0f, r, 1.0f);
}

// Warp-specialized block: 192 threads over 8 batches.
//   warps 0-1 (GEMM): gate pair g=wid, all 8 batches; no S-state.
//   warps 2-5 (tail): batches {2(w-2), 2(w-2)+1}; S-state + fre + elementwise.
// Per step: [barA] GEMM j-loop (tail overlaps fre matvec) -> gates STS ->
//           [barB] tail elementwise -> h publish -> [barA...]
__global__ __launch_bounds__(NT) void sfm_kernel(
    const float* __restrict__ x,
    const float* __restrict__ W_i,   const float* __restrict__ b_i,
    const float* __restrict__ W_ste, const float* __restrict__ b_ste,
    const float* __restrict__ W_fre, const float* __restrict__ U_fre, const float* __restrict__ b_fre,
    const float* __restrict__ W_c,   const float* __restrict__ b_c,
    const float* __restrict__ W_o,   const float* __restrict__ b_o,
    const float* __restrict__ U_a,   const float* __restrict__ b_a,
    const float* __restrict__ W_p,   const float* __restrict__ b_p,
    float* __restrict__ out)
{
    extern __shared__ __align__(16) uint4 shU[];        // [2][32][32] bf16 U, 32 KB

    __shared__ __align__(16) ull   sh_hd[Hh][NBB];      // dup (h,h) pairs [col][b], 4 KB
    __shared__ __align__(16) float sh_hp[NBB][Hh];      // plain h [b][col], 2 KB
    __shared__ __align__(16) ull   sh_gates[NBB][Hh][2];// {(i,ste),(c,o)} per cell, 8 KB
    __shared__ __align__(16) float sh_xs[Tt][Dd][NBB];  // x staged [t][d][b], 11.5 KB
    __shared__ __align__(16) float sh_UfT[Ff][66];      // [f][j], padded to 66 (bank spread)
    __shared__ ull sh_mpk[Tt];
    __shared__ __align__(16) ulonglong2 sh_tbld[16];    // {(cos,cos),(sin,sin)} dup pairs

    const int tid  = threadIdx.x;
    const int lane = tid & 31;
    const int wid  = tid >> 5;
    const int bbase = blockIdx.x * NBB;
    const int h0 = lane, h1 = lane + 32;

    // ---- one-time staging ----
    {
        const uint4* gsrc = &g_Ub4[0][0];
        for (int i = tid; i < 2048; i += NT) shU[i] = gsrc[i];
    }
    for (int i = tid; i < Tt * Dd * NBB; i += NT) {
        int t = i / (Dd * NBB), r = i % (Dd * NBB);
        int d = r / NBB, b = r % NBB;
        sh_xs[t][d][b] = x[(size_t)(bbase + b) * (Tt * Dd) + t * Dd + d];
    }
    for (int i = tid; i < Ff * Hh; i += NT) {
        int f = i >> 6, j = i & 63;
        sh_UfT[f][j] = U_fre[j * Ff + f];
    }
    for (int i = tid; i < Tt; i += NT) {
        ull v = 0;
#pragma unroll
        for (int f = 1; f < Ff; f++)
            v |= (ull)(((i + 1) * f) % Ff) << (4 * f);
        sh_mpk[i] = v;
    }
    if (tid < Ff) {
        float s, c;
        sincosf((float)tid * 0.62831853071795864769f, &s, &c);   // 2*pi/10
        sh_tbld[tid] = make_ulonglong2(pack2(c, c), pack2(s, s));
    }
    if (tid < Hh) {
#pragma unroll
        for (int b = 0; b < NBB; b++) sh_hd[tid][b] = 0ull;
    }
    for (int i = tid; i < NBB * Hh; i += NT)
        (&sh_hp[0][0])[i] = 0.0f;
    __syncthreads();

    if (wid < 2) {
        // ================= GEMM warp: gate pair g, 8 batches =================
        const int g = wid;
        const float* Wg0 = g ? W_c : W_i;
        const float* Wg1 = g ? W_o : W_ste;
        const float* bg0 = g ? b_c : b_i;
        const float* bg1 = g ? b_o : b_ste;
        ull Wp_[2][Dd];   // (g0,g1) pairs per [hslot][d]
#pragma unroll
        for (int d = 0; d < Dd; d++) {
            Wp_[0][d] = pack2(Wg0[d * Hh + h0], Wg1[d * Hh + h0]);
            Wp_[1][d] = pack2(Wg0[d * Hh + h1], Wg1[d * Hh + h1]);
        }
        const ull bp0 = pack2(bg0[h0], bg1[h0]);
        const ull bp1 = pack2(bg0[h1], bg1[h1]);
        const uint4* Ub = shU + g * 1024;

        for (int t = 0; t < Tt; t++) {
            // seeds: acc[hs][b] = bias + x_t @ (Wg0,Wg1)
            ull acc[2][NBB];
#pragma unroll
            for (int b = 0; b < NBB; b++) { acc[0][b] = bp0; acc[1][b] = bp1; }
#pragma unroll
            for (int d = 0; d < Dd; d++) {
                const float* xr = &sh_xs[t][d][0];
                float4 xa = *reinterpret_cast<const float4*>(xr);       // b0..b3
                float4 xb = *reinterpret_cast<const float4*>(xr + 4);   // b4..b7
                float xv[NBB] = {xa.x, xa.y, xa.z, xa.w, xb.x, xb.y, xb.z, xb.w};
#pragma unroll
                for (int b = 0; b < NBB; b++) {
                    ull xd = pack2(xv[b], xv[b]);
                    acc[0][b] = fma2(xd, Wp_[0][d], acc[0][b]);
                    acc[1][b] = fma2(xd, Wp_[1][d], acc[1][b]);
                }
            }
            // j-loop: paired bf16 U (1 LDS.128 per 2 j) x dup-h (4 LDS.128 per j)
#pragma unroll 4
            for (int jp = 0; jp < 32; jp++) {
                uint4 uu = Ub[jp * 32 + lane];
                int j0 = 2 * jp, j1 = 2 * jp + 1;
                {
                    ulonglong2 hA = *(const ulonglong2*)&sh_hd[j0][0];
                    ulonglong2 hB = *(const ulonglong2*)&sh_hd[j0][2];
                    ulonglong2 hC = *(const ulonglong2*)&sh_hd[j0][4];
                    ulonglong2 hD = *(const ulonglong2*)&sh_hd[j0][6];
                    ull u0 = bf2f2(uu.x);
                    ull u1 = bf2f2(uu.y);
                    acc[0][0] = fma2(hA.x, u0, acc[0][0]);
                    acc[1][0] = fma2(hA.x, u1, acc[1][0]);
                    acc[0][1] = fma2(hA.y, u0, acc[0][1]);
                    acc[1][1] = fma2(hA.y, u1, acc[1][1]);
                    acc[0][2] = fma2(hB.x, u0, acc[0][2]);
                    acc[1][2] = fma2(hB.x, u1, acc[1][2]);
                    acc[0][3] = fma2(hB.y, u0, acc[0][3]);
                    acc[1][3] = fma2(hB.y, u1, acc[1][3]);
                    acc[0][4] = fma2(hC.x, u0, acc[0][4]);
                    acc[1][4] = fma2(hC.x, u1, acc[1][4]);
                    acc[0][5] = fma2(hC.y, u0, acc[0][5]);
                    acc[1][5] = fma2(hC.y, u1, acc[1][5]);
                    acc[0][6] = fma2(hD.x, u0, acc[0][6]);
                    acc[1][6] = fma2(hD.x, u1, acc[1][6]);
                    acc[0][7] = fma2(hD.y, u0, acc[0][7]);
                    acc[1][7] = fma2(hD.y, u1, acc[1][7]);
                }
                {
                    ulonglong2 hA = *(const ulonglong2*)&sh_hd[j1][0];
                    ulonglong2 hB = *(const ulonglong2*)&sh_hd[j1][2];
                    ulonglong2 hC = *(const ulonglong2*)&sh_hd[j1][4];
                    ulonglong2 hD = *(const ulonglong2*)&sh_hd[j1][6];
                    ull u0 = bf2f2(uu.z);
                    ull u1 = bf2f2(uu.w);
                    acc[0][0] = fma2(hA.x, u0, acc[0][0]);
                    acc[1][0] = fma2(hA.x, u1, acc[1][0]);
                    acc[0][1] = fma2(hA.y, u0, acc[0][1]);
                    acc[1][1] = fma2(hA.y, u1, acc[1][1]);
                    acc[0][2] = fma2(hB.x, u0, acc[0][2]);
                    acc[1][2] = fma2(hB.x, u1, acc[1][2]);
                    acc[0][3] = fma2(hB.y, u0, acc[0][3]);
                    acc[1][3] = fma2(hB.y, u1, acc[1][3]);
                    acc[0][4] = fma2(hC.x, u0, acc[0][4]);
                    acc[1][4] = fma2(hC.x, u1, acc[1][4]);
                    acc[0][5] = fma2(hC.y, u0, acc[0][5]);
                    acc[1][5] = fma2(hC.y, u1, acc[1][5]);
                    acc[0][6] = fma2(hD.x, u0, acc[0][6]);
                    acc[1][6] = fma2(hD.x, u1, acc[1][6]);
                    acc[0][7] = fma2(hD.y, u0, acc[0][7]);
                    acc[1][7] = fma2(hD.y, u1, acc[1][7]);
                }
            }
            // publish my gate pair for all cells
#pragma unroll
            for (int b = 0; b < NBB; b++) {
                sh_gates[b][h0][g] = acc[0][b];
                sh_gates[b][h1][g] = acc[1][b];
            }
            __syncthreads();   // barB: gates ready
            __syncthreads();   // barA: h(t) published by tail
        }
        // GEMM warps: no epilogue work
    } else {
        // ================= tail warp tw: batches {2tw, 2tw+1} =================
        const int tw = wid - 2;
        const bool duty = (lane < 2 * Ff);
        const int fb = duty ? (lane / Ff) : 0;    // local batch of my duty cell
        const int ffq = lane % Ff;
        const int bglob = 2 * tw + fb;
        float wfre[Dd];
#pragma unroll
        for (int d = 0; d < Dd; d++) wfre[d] = W_fre[d * Ff + ffq];
        const float bfre = b_fre[ffq];
        const ull ba_p = pack2(b_a[h0], b_a[h1]);
        ull ua_d[Ff];
#pragma unroll
        for (int f = 0; f < Ff; f++) { float u = U_a[f]; ua_d[f] = pack2(u, u); }

        // hslot-packed oscillator state: sre_p[bl][f] = (sre@h0, sre@h1)
        ull sre_p[2][Ff], sim_p[2][Ff];
#pragma unroll
        for (int bl = 0; bl < 2; bl++)
#pragma unroll
            for (int f = 0; f < Ff; f++) { sre_p[bl][f] = 0ull; sim_p[bl][f] = 0ull; }
        float hlast[2][2] = {{0.f, 0.f}, {0.f, 0.f}};

        for (int t = 0; t < Tt; t++) {
            // --- phase A (overlaps GEMM): fre matvec from plain h(t-1) ---
            float af = bfre;
#pragma unroll
            for (int d = 0; d < Dd; d++)
                af = fmaf(sh_xs[t][d][bglob], wfre[d], af);
            {
                ull af2 = 0ull;
                const float* hpr = &sh_hp[bglob][0];
                const float* ufr = &sh_UfT[ffq][0];
#pragma unroll 8
                for (int jj = 0; jj < 32; jj++) {
                    ull hpp = *reinterpret_cast<const ull*>(hpr + 2 * jj);   // LDS.64
                    ull ufp = *reinterpret_cast<const ull*>(ufr + 2 * jj);   // LDS.64
                    af2 = fma2(hpp, ufp, af2);
                }
                float2 a2 = unpack2(af2);
                af += a2.x + a2.y;
            }
            const float frev = hsig(af);   // fre(t) on duty lanes
            __syncthreads();   // barB: gates ready
            // --- phase B: elementwise tail for my 2 batches ---
            const ull mp = sh_mpk[t];
#pragma unroll
            for (int bl = 0; bl < 2; bl++) {
                int b = 2 * tw + bl;
                ulonglong2 gt0 = *(const ulonglong2*)&sh_gates[b][h0][0];
                ulonglong2 gt1 = *(const ulonglong2*)&sh_gates[b][h1][0];
                float2 is0 = unpack2(gt0.x), co0 = unpack2(gt0.y);
                float2 is1 = unpack2(gt1.x), co1 = unpack2(gt1.y);
                float iv0 = hsig(is0.x), sv0 = hsig(is0.y), ov0 = hsig(co0.y);
                float iv1 = hsig(is1.x), sv1 = hsig(is1.y), ov1 = hsig(co1.y);
                float cv0 = iv0 * ftanh(co0.x);
                float cv1 = iv1 * ftanh(co1.x);
                ull sv_p = pack2(sv0, sv1);
                ull cv_p = pack2(cv0, cv1);
                ull acca_p = ba_p;
#pragma unroll
                for (int f = 0; f < Ff; f++) {
                    float frf = __shfl_sync(0xffffffffu, frev, bl * Ff + f);
                    ull fr_p = pack2(frf, frf);
                    ulonglong2 tb = sh_tbld[(int)((mp >> (4 * f)) & 15)];
                    ull fv = mul2(sv_p, fr_p);
                    ull r = fma2(fv, sre_p[bl][f], mul2(cv_p, tb.x));
                    ull m = fma2(fv, sim_p[bl][f], mul2(cv_p, tb.y));
                    sre_p[bl][f] = r;
                    sim_p[bl][f] = m;
                    ull A = fma2(m, m, mul2(r, r));
                    acca_p = fma2(A, ua_d[f], acca_p);
                }
                float2 acca = unpack2(acca_p);
                hlast[bl][0] = ov0 * ftanh(acca.x);
                hlast[bl][1] = ov1 * ftanh(acca.y);
                // publish h: dup pairs for GEMM, plain for fre
                sh_hd[h0][b] = pack2(hlast[bl][0], hlast[bl][0]);
                sh_hd[h1][b] = pack2(hlast[bl][1], hlast[bl][1]);
                sh_hp[b][h0] = hlast[bl][0];
                sh_hp[b][h1] = hlast[bl][1];
            }
            __syncthreads();   // barA: new h visible
        }

        // ---- projection: out[b] = h @ W_p + b_p (butterfly over my 2 batches) ----
        {
            float wp0 = W_p[h0], wp1 = W_p[h1];
            float p0 = fmaf(hlast[0][0], wp0, hlast[0][1] * wp1);
            float p1 = fmaf(hlast[1][0], wp0, hlast[1][1] * wp1);
            ull pp = pack2(p0, p1);
#pragma unroll
            for (int off = 16; off >= 1; off >>= 1)
                pp = add2(pp, __shfl_xor_sync(0xffffffffu, pp, off));
            if (lane == 0) {
                float2 r = unpack2(pp);
                float bpv = b_p[0];
                out[bbase + 2 * tw]     = r.x + bpv;
                out[bbase + 2 * tw + 1] = r.y + bpv;
            }
        }
    }
}

extern "C" void kernel_launch(void* const* d_in, const int* in_sizes, int n_in,
                              void* d_out, int out_size) {
    const float* x     = (const float*)d_in[0];
    const float* W_i   = (const float*)d_in[1];
    const float* U_i   = (const float*)d_in[2];
    const float* b_i   = (const float*)d_in[3];
    const float* W_ste = (const float*)d_in[4];
    const float* U_ste = (const float*)d_in[5];
    const float* b_ste = (const float*)d_in[6];
    const float* W_fre = (const float*)d_in[7];
    const float* U_fre = (const float*)d_in[8];
    const float* b_fre = (const float*)d_in[9];
    const float* W_c   = (const float*)d_in[10];
    const float* U_c   = (const float*)d_in[11];
    const float* b_c   = (const float*)d_in[12];
    const float* W_o   = (const float*)d_in[13];
    const float* U_o   = (const float*)d_in[14];
    const float* b_o   = (const float*)d_in[15];
    const float* U_a   = (const float*)d_in[16];
    const float* b_a   = (const float*)d_in[17];
    const float* W_p   = (const float*)d_in[18];
    const float* b_p   = (const float*)d_in[19];

    (void)in_sizes; (void)n_in; (void)out_size;

    static int inited = 0;
    if (!inited) {
        cudaFuncSetAttribute(sfm_kernel, cudaFuncAttributeMaxDynamicSharedMemorySize, 32768);
        inited = 1;
    }

    prep_kernel<<<(2 * 32 * 32 + 255) / 256, 256>>>(U_i, U_ste, U_c, U_o);
    sfm_kernel<<<Bb / NBB, NT, 32768>>>(x, W_i, b_i, W_ste, b_ste, W_fre, U_fre, b_fre,
                                        W_c, b_c, W_o, b_o, U_a, b_a, W_p, b_p,
                                        (float*)d_out);
}

// round 17
// speedup vs baseline: 3.5172x; 2.3407x over previous
#include <cuda_runtime.h>
#include <cuda_fp16.h>
#include <cstdint>
#include <math.h>

#define Tt 60
#define Dd 6
#define Ff 10
#define Hh 64
#define NB 8            // batches per block
#define NT 256          // 8 warps
#define Bb 2048
#define MROWS 272       // 256 gate rows + 10 fre + 6 pad  (17 m16 tiles)
#define KDIM 80         // 64 U + 6 W + 1 bias + 9 pad     (5 k16 steps)
#define KPAD 88         // shared-stride pad (conflict-free frag loads)

typedef unsigned long long ull;
typedef unsigned int u32;

// Fused fp16 A matrix [MROWS][KDIM], row-major:
//   row r<256: gate g=r>>6 (i,ste,c,o), col h=r&63:
//     k<64: U_g[k][h]; 64..69: W_g[k-64][h]; 70: b_g[h]; else 0
//   row 256+f (f<10): same for fre (U_fre/W_fre/b_fre)
__device__ __align__(16) __half g_A16[MROWS * KDIM];

__global__ void prep_kernel(
    const float* __restrict__ Ui, const float* __restrict__ Us,
    const float* __restrict__ Uc, const float* __restrict__ Uo,
    const float* __restrict__ Wi, const float* __restrict__ Ws,
    const float* __restrict__ Wc, const float* __restrict__ Wo,
    const float* __restrict__ bi, const float* __restrict__ bs,
    const float* __restrict__ bc, const float* __restrict__ bo,
    const float* __restrict__ Ufre, const float* __restrict__ Wfre,
    const float* __restrict__ bfre)
{
    int idx = blockIdx.x * blockDim.x + threadIdx.x;
    if (idx >= MROWS * KDIM) return;
    int r = idx / KDIM, k = idx % KDIM;
    float v = 0.0f;
    if (r < 256) {
        int g = r >> 6, h = r & 63;
        const float* U = (g == 0) ? Ui : (g == 1) ? Us : (g == 2) ? Uc : Uo;
        const float* W = (g == 0) ? Wi : (g == 1) ? Ws : (g == 2) ? Wc : Wo;
        const float* B = (g == 0) ? bi : (g == 1) ? bs : (g == 2) ? bc : bo;
        if (k < 64) v = U[k * Hh + h];
        else if (k < 70) v = W[(k - 64) * Hh + h];
        else if (k == 70) v = B[h];
    } else if (r < 266) {
        int f = r - 256;
        if (k < 64) v = Ufre[k * Ff + f];
        else if (k < 70) v = Wfre[(k - 64) * Ff + f];
        else if (k == 70) v = bfre[f];
    }
    g_A16[idx] = __float2half(v);
}

__device__ __forceinline__ float hsig(float v) {
    return __saturatef(fmaf(v, 0.16666667f, 0.5f));
}
__device__ __forceinline__ float ftanh(float x) {
    float e = __expf(2.0f * x);
    float r;
    asm("rcp.approx.f32 %0, %1;" : "=f"(r) : "f"(e + 1.0f));
    return fmaf(-2.0f, r, 1.0f);
}
__device__ __forceinline__ ull pack2(float lo, float hi) {
    ull r; asm("mov.b64 %0, {%1, %2};" : "=l"(r) : "f"(lo), "f"(hi)); return r;
}
__device__ __forceinline__ ull fma2(ull a, ull b, ull c) {
    ull d; asm("fma.rn.f32x2 %0, %1, %2, %3;" : "=l"(d) : "l"(a), "l"(b), "l"(c)); return d;
}
__device__ __forceinline__ ull mul2(ull a, ull b) {
    ull d; asm("mul.rn.f32x2 %0, %1, %2;" : "=l"(d) : "l"(a), "l"(b)); return d;
}
__device__ __forceinline__ float2 unpack2(ull v) {
    float lo, hi; asm("mov.b64 {%0, %1}, %2;" : "=f"(lo), "=f"(hi) : "l"(v));
    return make_float2(lo, hi);
}
__device__ __forceinline__ void hmma(float& d0, float& d1, float& d2, float& d3,
                                     u32 a0, u32 a1, u32 a2, u32 a3, u32 b0, u32 b1) {
    asm volatile("mma.sync.aligned.m16n8k16.row.col.f32.f16.f16.f32 "
        "{%0,%1,%2,%3}, {%4,%5,%6,%7}, {%8,%9}, {%0,%1,%2,%3};"
        : "+f"(d0), "+f"(d1), "+f"(d2), "+f"(d3)
        : "r"(a0), "r"(a1), "r"(a2), "r"(a3), "r"(b0), "r"(b1));
}

// Block = 256 threads = 8 warps over NB=8 batches.
// Phase A (all warps): warp w computes m16 tiles {w, w+8} (+16 for w=7) of
//   D[272 x 8] = A[272 x 80] @ B[80 x 8] via mma.sync; gates -> shared.
// Phase B (all warps): thread owns (h = tid&63, batches {2bp, 2bp+1}, bp=tid>>6);
//   elementwise tail, S-state batch-packed f32x2; publishes h (fp16) into B.
__global__ __launch_bounds__(NT) void sfm_kernel(
    const float* __restrict__ x,
    const float* __restrict__ U_a, const float* __restrict__ b_a,
    const float* __restrict__ W_p, const float* __restrict__ b_p,
    float* __restrict__ out)
{
    extern __shared__ __align__(16) __half shA[];       // [MROWS][KPAD], 47872 B

    __shared__ __align__(16) __half shB[NB][KPAD];      // B: [n][k], 1408 B
    __shared__ __align__(16) float  shG[MROWS][10];     // gates [row][8b+pad], 10880 B
    __shared__ __align__(16) __half shX[Tt][48];        // x fp16 [t][d*8+b]
    __shared__ __align__(16) float  shHf[NB][66];       // final h f32 for projection
    __shared__ ull sh_mpk[Tt];
    __shared__ __align__(16) ulonglong2 sh_tbld[16];    // {(c,c),(s,s)} dup pairs
    __shared__ __align__(16) ull sh_uad[Ff];            // (ua,ua) dup pairs

    const int tid  = threadIdx.x;
    const int lane = tid & 31;
    const int w    = tid >> 5;
    const int bbase = blockIdx.x * NB;
    const int gID = lane >> 2;      // 0..7
    const int tg  = lane & 3;       // 0..3

    // ---- one-time staging ----
    for (int i = tid; i < MROWS * KPAD; i += NT) {
        int r = i / KPAD, k = i % KPAD;
        shA[i] = (k < KDIM) ? g_A16[r * KDIM + k] : __float2half(0.0f);
    }
    {   // B zero
        u32* bz = reinterpret_cast<u32*>(&shB[0][0]);
        for (int i = tid; i < NB * KPAD / 2; i += NT) bz[i] = 0u;
    }
    for (int i = tid; i < Tt * 48; i += NT) {
        int t = i / 48, r = i % 48;
        int d = r >> 3, b = r & 7;
        shX[t][r] = __float2half(x[(size_t)(bbase + b) * (Tt * Dd) + t * Dd + d]);
    }
    for (int i = tid; i < Tt; i += NT) {
        ull v = 0;
#pragma unroll
        for (int f = 1; f < Ff; f++)
            v |= (ull)(((i + 1) * f) % Ff) << (4 * f);
        sh_mpk[i] = v;
    }
    if (tid < Ff) {
        float s, c;
        sincosf((float)tid * 0.62831853071795864769f, &s, &c);   // 2*pi/10
        sh_tbld[tid] = make_ulonglong2(pack2(c, c), pack2(s, s));
        float u = U_a[tid];
        sh_uad[tid] = pack2(u, u);
    }
    __syncthreads();
    // B const rows: ones at k=70; x(t=0) at k=64..69
    if (tid < NB) shB[tid][70] = __float2half(1.0f);
    if (tid < 48) {
        int d = tid >> 3, b = tid & 7;
        shB[b][64 + d] = shX[0][tid];
    }

    // ---- per-thread identities ----
    const int nT = (w == 7) ? 3 : 2;
    int tlist[3];
    tlist[0] = w; tlist[1] = w + 8; tlist[2] = 16;

    const int h  = tid & 63;
    const int bp = tid >> 6;                  // batch pair 0..3
    const ull ba_p = pack2(b_a[h], b_a[h]);
    const char* gbase = reinterpret_cast<const char*>(&shG[0][0]);
    char* gbase_w = reinterpret_cast<char*>(&shG[0][0]);

    // S-state, batch-packed: sre_p[f] = (s@b0, s@b1)
    ull sre_p[Ff], sim_p[Ff];
#pragma unroll
    for (int f = 0; f < Ff; f++) { sre_p[f] = 0ull; sim_p[f] = 0ull; }
    float hv0 = 0.0f, hv1 = 0.0f;

    __syncthreads();

    for (int t = 0; t < Tt; t++) {
        // ================= phase A: fused GEMM =================
        // B fragments (shared by all my tiles): b[kk][0/1]
        u32 bf[5][2];
#pragma unroll
        for (int kk = 0; kk < 5; kk++) {
            const char* bb = reinterpret_cast<const char*>(&shB[gID][0]);
            bf[kk][0] = *reinterpret_cast<const u32*>(bb + (kk * 16 + tg * 2) * 2);
            bf[kk][1] = *reinterpret_cast<const u32*>(bb + (kk * 16 + tg * 2 + 8) * 2);
        }
        for (int it = 0; it < nT; it++) {
            int R0 = tlist[it] * 16;
            float d0 = 0.f, d1 = 0.f, d2 = 0.f, d3 = 0.f;
            const char* ar0 = reinterpret_cast<const char*>(shA) + (R0 + gID) * (KPAD * 2);
            const char* ar1 = ar0 + 8 * (KPAD * 2);
#pragma unroll
            for (int kk = 0; kk < 5; kk++) {
                int ko = (kk * 16 + tg * 2) * 2;
                u32 a0 = *reinterpret_cast<const u32*>(ar0 + ko);
                u32 a1 = *reinterpret_cast<const u32*>(ar1 + ko);
                u32 a2 = *reinterpret_cast<const u32*>(ar0 + ko + 16);
                u32 a3 = *reinterpret_cast<const u32*>(ar1 + ko + 16);
                hmma(d0, d1, d2, d3, a0, a1, a2, a3, bf[kk][0], bf[kk][1]);
            }
            // store gates: rows R0+gID, R0+gID+8; cols (batches) tg*2, tg*2+1
            *reinterpret_cast<float2*>(gbase_w + (R0 + gID) * 40 + tg * 8) =
                make_float2(d0, d1);
            *reinterpret_cast<float2*>(gbase_w + (R0 + gID + 8) * 40 + tg * 8) =
                make_float2(d2, d3);
        }
        __syncthreads();   // gates visible; B frag reads done

        // ================= phase B: elementwise tail =================
        // gates for (h, b0),(h, b1): rows g*64+h, byte col bp*8
        ull g_i = *reinterpret_cast<const ull*>(gbase + (0 * 64 + h) * 40 + bp * 8);
        ull g_s = *reinterpret_cast<const ull*>(gbase + (1 * 64 + h) * 40 + bp * 8);
        ull g_c = *reinterpret_cast<const ull*>(gbase + (2 * 64 + h) * 40 + bp * 8);
        ull g_o = *reinterpret_cast<const ull*>(gbase + (3 * 64 + h) * 40 + bp * 8);
        float2 vi = unpack2(g_i), vs = unpack2(g_s), vc = unpack2(g_c), vo = unpack2(g_o);
        float iv0 = hsig(vi.x), iv1 = hsig(vi.y);
        float sv0 = hsig(vs.x), sv1 = hsig(vs.y);
        float ov0 = hsig(vo.x), ov1 = hsig(vo.y);
        float cv0 = iv0 * ftanh(vc.x);
        float cv1 = iv1 * ftanh(vc.y);
        ull sv_p = pack2(sv0, sv1);
        ull cv_p = pack2(cv0, cv1);
        ull acca_p = ba_p;
        const ull mp = sh_mpk[t];
#pragma unroll
        for (int f = 0; f < Ff; f++) {
            ull frr = *reinterpret_cast<const ull*>(gbase + (256 + f) * 40 + bp * 8);
            float2 fv2 = unpack2(frr);
            ull fr_p = pack2(hsig(fv2.x), hsig(fv2.y));
            ulonglong2 tb = sh_tbld[(int)((mp >> (4 * f)) & 15)];
            ull fv = mul2(sv_p, fr_p);
            ull r = fma2(fv, sre_p[f], mul2(cv_p, tb.x));
            ull m = fma2(fv, sim_p[f], mul2(cv_p, tb.y));
            sre_p[f] = r;
            sim_p[f] = m;
            ull A = fma2(m, m, mul2(r, r));
            acca_p = fma2(A, sh_uad[f], acca_p);
        }
        float2 acca = unpack2(acca_p);
        hv0 = ov0 * ftanh(acca.x);
        hv1 = ov1 * ftanh(acca.y);

        // publish h (fp16) into B rows 0-63
        shB[2 * bp][h]     = __float2half(hv0);
        shB[2 * bp + 1][h] = __float2half(hv1);
        // x for next step
        if (tid < 48 && t + 1 < Tt) {
            int d = tid >> 3, b = tid & 7;
            shB[b][64 + d] = shX[t + 1][tid];
        }
        if (t == Tt - 1) {
            shHf[2 * bp][h]     = hv0;
            shHf[2 * bp + 1][h] = hv1;
        }
        __syncthreads();   // B ready for next step
    }

    // ---- projection: warp w handles batch w ----
    if (w < NB) {
        float p = fmaf(shHf[w][lane], W_p[lane], shHf[w][lane + 32] * W_p[lane + 32]);
#pragma unroll
        for (int off = 16; off >= 1; off >>= 1)
            p += __shfl_xor_sync(0xffffffffu, p, off);
        if (lane == 0) out[bbase + w] = p + b_p[0];
    }
}

extern "C" void kernel_launch(void* const* d_in, const int* in_sizes, int n_in,
                              void* d_out, int out_size) {
    const float* x     = (const float*)d_in[0];
    const float* W_i   = (const float*)d_in[1];
    const float* U_i   = (const float*)d_in[2];
    const float* b_i   = (const float*)d_in[3];
    const float* W_ste = (const float*)d_in[4];
    const float* U_ste = (const float*)d_in[5];
    const float* b_ste = (const float*)d_in[6];
    const float* W_fre = (const float*)d_in[7];
    const float* U_fre = (const float*)d_in[8];
    const float* b_fre = (const float*)d_in[9];
    const float* W_c   = (const float*)d_in[10];
    const float* U_c   = (const float*)d_in[11];
    const float* b_c   = (const float*)d_in[12];
    const float* W_o   = (const float*)d_in[13];
    const float* U_o   = (const float*)d_in[14];
    const float* b_o   = (const float*)d_in[15];
    const float* U_a   = (const float*)d_in[16];
    const float* b_a   = (const float*)d_in[17];
    const float* W_p   = (const float*)d_in[18];
    const float* b_p   = (const float*)d_in[19];

    (void)in_sizes; (void)n_in; (void)out_size;

    static int inited = 0;
    if (!inited) {
        cudaFuncSetAttribute(sfm_kernel, cudaFuncAttributeMaxDynamicSharedMemorySize,
                             MROWS * KPAD * 2);
        inited = 1;
    }

    prep_kernel<<<(MROWS * KDIM + 255) / 256, 256>>>(
        U_i, U_ste, U_c, U_o, W_i, W_ste, W_c, W_o,
        b_i, b_ste, b_c, b_o, U_fre, W_fre, b_fre);
    sfm_kernel<<<Bb / NB, NT, MROWS * KPAD * 2>>>(x, U_a, b_a, W_p, b_p, (float*)d_out);
}